// round 4
// baseline (speedup 1.0000x reference)
#include <cuda_runtime.h>

#define Bb 8
#define Nn 2048
#define Kk 256
#define Ff 128
#define NCH 32
#define CSZ 64

// -------- scratch (device globals; no allocation allowed) --------
__device__ float g_Wh[Bb*Nn*Ff];
__device__ float g_u [Bb*Nn];
__device__ float g_v [Bb*Nn];
__device__ float g_key[Bb*Nn];      // sorted ascending keys = -v
__device__ int   g_perm[Bb*Nn];
__device__ float g_Ej [Bb*Nn];      // exp(v_sorted)
__device__ float g_Fj [Bb*Nn];      // exp(0.01*v_sorted)
__device__ float g_PzE[Bb*Nn];      // global inclusive scalar prefix of Ej
__device__ float g_PzF[Bb*Nn];
__device__ float g_PE [Bb*Nn*Ff];   // chunk-local inclusive prefixes
__device__ float g_PF [Bb*Nn*Ff];
__device__ float g_chE[Bb*Ff*NCH];  // TRANSPOSED: [b][f][chunk]
__device__ float g_chF[Bb*Ff*NCH];
__device__ float g_offE[Bb*NCH*Ff]; // exclusive chunk offsets [b][chunk][f]
__device__ float g_offF[Bb*NCH*Ff];
__device__ float g_TF [Bb*Ff];      // total of F-branch vector sums

// ================= Kernel A: Wh = h@W, u = Wh.a_i, v = Wh.a_j =================
// block (16,16) = 256 thr, tile 128 rows x 128 cols, thread: 8 rows x 8 cols
#define KC 16
__global__ __launch_bounds__(256, 2)
void gemm_uv(const float* __restrict__ h, const float* __restrict__ W,
             const float* __restrict__ ai, const float* __restrict__ aj) {
    __shared__ float Ws[KC][Ff];     // 8 KB
    __shared__ float hs[KC][132];    // 8.25 KB, padded for f4 align + fewer STS conflicts
    int tx = threadIdx.x;            // 0..15 -> cols 8tx..8tx+7
    int ty = threadIdx.y;            // 0..15 -> rows 8ty..8ty+7
    int t  = ty*16 + tx;
    int b  = blockIdx.y;
    int row0 = blockIdx.x * 128;
    const float* hB = h + ((size_t)b*Nn + row0) * Kk;

    float acc[8][8];
    #pragma unroll
    for (int r=0;r<8;r++)
        #pragma unroll
        for (int c=0;c<8;c++) acc[r][c]=0.f;

    for (int kc=0; kc<Kk; kc+=KC) {
        // stage W chunk: 16x128 = 512 float4, 2 per thread
        #pragma unroll
        for (int i=0;i<2;i++){
            int idx = t + i*256;
            int r = idx >> 5, c4 = idx & 31;
            ((float4*)&Ws[r][0])[c4] = ((const float4*)&W[(size_t)(kc+r)*Ff])[c4];
        }
        // stage h chunk transposed: 128 rows x 16 k, 8 scalars per thread
        #pragma unroll
        for (int i=0;i<8;i++){
            int idx = t + i*256;
            int kl = idx & (KC-1);
            int r  = idx >> 4;
            hs[kl][r] = hB[(size_t)r*Kk + kc + kl];
        }
        __syncthreads();
        #pragma unroll
        for (int kk=0; kk<KC; kk++){
            float4 w0 = *(const float4*)&Ws[kk][tx*8];
            float4 w1 = *(const float4*)&Ws[kk][tx*8+4];
            float4 h0 = *(const float4*)&hs[kk][ty*8];
            float4 h1 = *(const float4*)&hs[kk][ty*8+4];
            float wv[8] = {w0.x,w0.y,w0.z,w0.w,w1.x,w1.y,w1.z,w1.w};
            float hv[8] = {h0.x,h0.y,h0.z,h0.w,h1.x,h1.y,h1.z,h1.w};
            #pragma unroll
            for (int r=0;r<8;r++)
                #pragma unroll
                for (int c=0;c<8;c++)
                    acc[r][c] = fmaf(hv[r], wv[c], acc[r][c]);
        }
        __syncthreads();
    }

    float av[8], bv[8];
    #pragma unroll
    for (int c=0;c<8;c++){ av[c]=ai[tx*8+c]; bv[c]=aj[tx*8+c]; }
    #pragma unroll
    for (int r=0;r<8;r++){
        int rg = row0 + ty*8 + r;
        float4 o0, o1;
        o0.x=acc[r][0]; o0.y=acc[r][1]; o0.z=acc[r][2]; o0.w=acc[r][3];
        o1.x=acc[r][4]; o1.y=acc[r][5]; o1.z=acc[r][6]; o1.w=acc[r][7];
        float* wp = &g_Wh[((size_t)b*Nn + rg)*Ff + tx*8];
        *(float4*)wp = o0; *(float4*)(wp+4) = o1;
        float pu=0.f, pv=0.f;
        #pragma unroll
        for (int c=0;c<8;c++){ pu = fmaf(acc[r][c], av[c], pu); pv = fmaf(acc[r][c], bv[c], pv); }
        // reduce across the 16 tx lanes (warp = 2 ty groups of 16 lanes)
        #pragma unroll
        for (int s=8;s>0;s>>=1){
            pu += __shfl_xor_sync(0xffffffffu, pu, s);
            pv += __shfl_xor_sync(0xffffffffu, pv, s);
        }
        if (tx==0){ g_u[b*Nn+rg]=pu; g_v[b*Nn+rg]=pv; }
    }
}

// ================= Kernel B: per-batch bitonic sort on key=-v + scalar scans ==
__global__ void sort_scan() {
    __shared__ float skey[2048];
    __shared__ int   sidx[2048];
    __shared__ float sa[2048];
    __shared__ float sb[2048];
    __shared__ float st[2048];
    int b = blockIdx.x;
    int tid = threadIdx.x; // 1024

    for (int e=tid; e<2048; e+=1024){ skey[e] = -g_v[b*Nn+e]; sidx[e]=e; }
    __syncthreads();

    for (int k=2;k<=2048;k<<=1){
        for (int j=k>>1;j>0;j>>=1){
            for (int e=tid;e<2048;e+=1024){
                int ixj = e ^ j;
                if (ixj > e){
                    bool up = ((e & k) == 0);
                    float a=skey[e], c=skey[ixj];
                    if ((a > c) == up){
                        skey[e]=c; skey[ixj]=a;
                        int t1=sidx[e]; sidx[e]=sidx[ixj]; sidx[ixj]=t1;
                    }
                }
            }
            __syncthreads();
        }
    }

    for (int e=tid;e<2048;e+=1024){
        float kv = skey[e];
        float vv = -kv;
        float Ejv = __expf(vv);
        float Fjv = __expf(0.01f*vv);
        g_key [b*Nn+e]=kv;  g_perm[b*Nn+e]=sidx[e];
        g_Ej  [b*Nn+e]=Ejv; g_Fj  [b*Nn+e]=Fjv;
        sa[e]=Ejv; sb[e]=Fjv;
    }
    __syncthreads();

    // inclusive Hillis-Steele scan of sa (ping-pong with st)
    {
        float* src = sa; float* dst = st;
        for (int d=1; d<2048; d<<=1){
            for (int e=tid;e<2048;e+=1024)
                dst[e] = src[e] + (e>=d ? src[e-d] : 0.f);
            __syncthreads();
            float* tp=src; src=dst; dst=tp;
        }
        for (int e=tid;e<2048;e+=1024) g_PzE[b*Nn+e] = src[e];
        __syncthreads();
    }
    // scan of sb (ping-pong with sa, now free)
    {
        float* src = sb; float* dst = sa;
        for (int d=1; d<2048; d<<=1){
            for (int e=tid;e<2048;e+=1024)
                dst[e] = src[e] + (e>=d ? src[e-d] : 0.f);
            __syncthreads();
            float* tp=src; src=dst; dst=tp;
        }
        for (int e=tid;e<2048;e+=1024) g_PzF[b*Nn+e] = src[e];
    }
}

// ============ Kernel C1: chunk-local vector prefixes of Ej*Wh, Fj*Wh ==========
__global__ void prefix_chunks() {
    __shared__ int   sperm[CSZ];
    __shared__ float sE[CSZ], sF[CSZ];
    int b = blockIdx.y, ch = blockIdx.x, f = threadIdx.x; // 128 thr
    int base = ch*CSZ;
    if (f < CSZ){
        sperm[f]=g_perm[b*Nn+base+f];
        sE[f]=g_Ej[b*Nn+base+f];
        sF[f]=g_Fj[b*Nn+base+f];
    }
    __syncthreads();
    float ae=0.f, af=0.f;
    #pragma unroll 4
    for (int m=0;m<CSZ;m++){
        int j = sperm[m];
        float w = g_Wh[((size_t)b*Nn + j)*Ff + f];
        ae = fmaf(sE[m], w, ae);
        af = fmaf(sF[m], w, af);
        size_t o = ((size_t)b*Nn + base + m)*Ff + f;
        g_PE[o]=ae; g_PF[o]=af;
    }
    // transposed layout for the warp-scan kernel
    g_chE[((size_t)b*Ff+f)*NCH+ch]=ae;
    g_chF[((size_t)b*Ff+f)*NCH+ch]=af;
}

// ======== Kernel C2: warp-parallel exclusive scan of chunk totals =============
// grid Bb, block (32,32): lane = chunk, (ty, i) covers 128 features
__global__ void scan_chunks(){
    int b=blockIdx.x;
    int lane=threadIdx.x, ty=threadIdx.y;
    #pragma unroll
    for (int i=0;i<4;i++){
        int f = ty + 32*i;
        float ev = g_chE[((size_t)b*Ff+f)*NCH + lane];
        float fv = g_chF[((size_t)b*Ff+f)*NCH + lane];
        float ie = ev, iff = fv;
        #pragma unroll
        for (int s=1;s<32;s<<=1){
            float te = __shfl_up_sync(0xffffffffu, ie, s);
            float tf = __shfl_up_sync(0xffffffffu, iff, s);
            if (lane>=s){ ie+=te; iff+=tf; }
        }
        g_offE[((size_t)b*NCH+lane)*Ff+f] = ie - ev;
        g_offF[((size_t)b*NCH+lane)*Ff+f] = iff - fv;
        if (lane==31) g_TF[b*Ff+f] = iff;
    }
}

// ================= Kernel D: binary search + combine ==========================
__global__ void finalize(float* __restrict__ out){
    __shared__ float skey[2048];
    int b  = blockIdx.y;
    int tx = threadIdx.x;  // 128 (feature)
    int ty = threadIdx.y;  // 8 rows per block
    int t  = ty*128+tx;
    for (int e=t; e<2048; e+=1024) skey[e]=g_key[b*Nn+e];
    __syncthreads();

    int row = blockIdx.x*8 + ty;
    float uu = g_u[b*Nn+row];
    int lo=0, hi=2048;
    while (lo<hi){ int mid=(lo+hi)>>1; if (skey[mid] < uu) lo=mid+1; else hi=mid; }
    int k = lo;  // count of v_j > -u_i  (E-branch prefix length)

    float Ei = __expf(uu), Fi = __expf(0.01f*uu);
    float TFf = g_TF[b*Ff+tx];
    float TzF = g_PzF[b*Nn + 2047];

    float pe=0.f, pf=0.f, pze=0.f, pzf=0.f;
    if (k>0){
        int km = k-1, c = km>>6; // /CSZ
        size_t o = ((size_t)b*Nn+km)*Ff+tx;
        pe  = g_PE[o] + g_offE[(b*NCH+c)*Ff+tx];
        pf  = g_PF[o] + g_offF[(b*NCH+c)*Ff+tx];
        pze = g_PzE[b*Nn+km];
        pzf = g_PzF[b*Nn+km];
    }
    float num = Ei*pe + Fi*(TFf - pf);
    float den = Ei*pze + Fi*(TzF - pzf);
    out[((size_t)b*Nn+row)*Ff+tx] = num/den;
}

// ================= launch =================
extern "C" void kernel_launch(void* const* d_in, const int* in_sizes, int n_in,
                              void* d_out, int out_size) {
    const float* h  = (const float*)d_in[0];
    const float* W  = (const float*)d_in[1];
    const float* ai = (const float*)d_in[2];
    const float* aj = (const float*)d_in[3];
    float* out = (float*)d_out;

    gemm_uv      <<<dim3(Nn/128, Bb), dim3(16,16)>>>(h, W, ai, aj);
    sort_scan    <<<Bb, 1024>>>();
    prefix_chunks<<<dim3(NCH, Bb), 128>>>();
    scan_chunks  <<<Bb, dim3(32,32)>>>();
    finalize     <<<dim3(Nn/8, Bb), dim3(128,8)>>>(out);
}

// round 6
// speedup vs baseline: 1.1026x; 1.1026x over previous
#include <cuda_runtime.h>
#include <cuda_bf16.h>
#include <cstdint>

#define Bb 8
#define Nn 2048
#define Kk 256
#define Ff 128
#define NCH 32
#define CSZ 64

// -------- scratch (device globals; no allocation allowed) --------
__device__ float g_Wh[Bb*Nn*Ff];
__device__ float g_u [Bb*Nn];
__device__ float g_v [Bb*Nn];
__device__ float g_wa_i[Kk];
__device__ float g_wa_j[Kk];
__device__ float g_key[Bb*Nn];
__device__ int   g_perm[Bb*Nn];
__device__ float g_Ej [Bb*Nn];
__device__ float g_Fj [Bb*Nn];
__device__ float g_PzE[Bb*Nn];
__device__ float g_PzF[Bb*Nn];
__device__ float g_PE [Bb*Nn*Ff];
__device__ float g_PF [Bb*Nn*Ff];
__device__ float g_chE[Bb*Ff*NCH];  // [b][f][chunk]
__device__ float g_chF[Bb*Ff*NCH];
__device__ float g_offE[Bb*NCH*Ff]; // [b][chunk][f]
__device__ float g_offF[Bb*NCH*Ff];
__device__ float g_TF [Bb*Ff];

// ================= helpers =================
__device__ __forceinline__ uint32_t smem_u32(const void* p){
    uint32_t a;
    asm("{ .reg .u64 t; cvta.to.shared.u64 t, %1; cvt.u32.u64 %0, t; }" : "=r"(a) : "l"(p));
    return a;
}
__device__ __forceinline__ void ldsm_x4(uint32_t* r, uint32_t addr){
    asm volatile("ldmatrix.sync.aligned.m8n8.x4.shared.b16 {%0,%1,%2,%3}, [%4];"
        : "=r"(r[0]),"=r"(r[1]),"=r"(r[2]),"=r"(r[3]) : "r"(addr));
}
__device__ __forceinline__ void ldsm_x4t(uint32_t* r, uint32_t addr){
    asm volatile("ldmatrix.sync.aligned.m8n8.x4.trans.shared.b16 {%0,%1,%2,%3}, [%4];"
        : "=r"(r[0]),"=r"(r[1]),"=r"(r[2]),"=r"(r[3]) : "r"(addr));
}
__device__ __forceinline__ void mma16816(float* d, const uint32_t* a, const uint32_t* b){
    asm volatile("mma.sync.aligned.m16n8k16.row.col.f32.bf16.bf16.f32 "
        "{%0,%1,%2,%3}, {%4,%5,%6,%7}, {%8,%9}, {%0,%1,%2,%3};"
        : "+f"(d[0]),"+f"(d[1]),"+f"(d[2]),"+f"(d[3])
        : "r"(a[0]),"r"(a[1]),"r"(a[2]),"r"(a[3]), "r"(b[0]),"r"(b[1]));
}

// smem layout for gemm (bytes)
#define AP 72                       // A row pitch in bf16 (64 + 8 pad)
#define BP 136                      // B row pitch in bf16 (128 + 8 pad)
#define OFF_AHI 0
#define OFF_ALO 18432               // 128*72*2
#define OFF_BHI 36864
#define OFF_BLO 54272               // +64*136*2
#define SM_GEMM 71680

// ======== Kernel W0: wa = W @ a (warp per W row) ========
__global__ void wa_kernel(const float* __restrict__ W,
                          const float* __restrict__ ai, const float* __restrict__ aj){
    int wid = (blockIdx.x*256 + threadIdx.x) >> 5;   // 0..255 = k row
    int lane = threadIdx.x & 31;
    const float* wr = &W[(size_t)wid*Ff];
    float pu=0.f, pv=0.f;
    #pragma unroll
    for (int q=0;q<4;q++){
        int n = lane + q*32;
        float w = wr[n];
        pu = fmaf(w, ai[n], pu);
        pv = fmaf(w, aj[n], pv);
    }
    #pragma unroll
    for (int s=16;s>0;s>>=1){
        pu += __shfl_xor_sync(0xffffffffu, pu, s);
        pv += __shfl_xor_sync(0xffffffffu, pv, s);
    }
    if (lane==0){ g_wa_i[wid]=pu; g_wa_j[wid]=pv; }
}

// ======== Kernel W1: u,v = h @ wa (warp per row) ========
__global__ __launch_bounds__(256)
void uv_kernel(const float* __restrict__ h){
    int row = blockIdx.x*8 + (threadIdx.x>>5);       // 0..16383
    int lane = threadIdx.x & 31;
    const float4* hr = (const float4*)&h[(size_t)row*Kk];
    float pu=0.f, pv=0.f;
    #pragma unroll
    for (int q=0;q<2;q++){
        int i4 = lane + q*32;
        float4 x = hr[i4];
        const float* wi = &g_wa_i[i4*4];
        const float* wj = &g_wa_j[i4*4];
        pu = fmaf(x.x,wi[0],fmaf(x.y,wi[1],fmaf(x.z,wi[2],fmaf(x.w,wi[3],pu))));
        pv = fmaf(x.x,wj[0],fmaf(x.y,wj[1],fmaf(x.z,wj[2],fmaf(x.w,wj[3],pv))));
    }
    #pragma unroll
    for (int s=16;s>0;s>>=1){
        pu += __shfl_xor_sync(0xffffffffu, pu, s);
        pv += __shfl_xor_sync(0xffffffffu, pv, s);
    }
    if (lane==0){ g_u[row]=pu; g_v[row]=pv; }
}

// ============ Kernel A: Wh = h@W (split-bf16 mma.sync) ============
// CTA 128x128, 8 warps: warp_m = wid&1 (64 rows), warp_n = wid>>1 (32 cols)
__global__ __launch_bounds__(256)
void gemm_mma(const float* __restrict__ h, const float* __restrict__ W){
    extern __shared__ char smem[];
    uint32_t sb = smem_u32(smem);
    int tid = threadIdx.x;
    int wid = tid >> 5, lane = tid & 31;
    int warp_m = wid & 1, warp_n = wid >> 1;
    int b = blockIdx.y;
    int row0 = blockIdx.x * 128;
    const float* hB = h + ((size_t)b*Nn + row0) * Kk;

    float acc[4][4][4];
    #pragma unroll
    for (int mt=0;mt<4;mt++)
        #pragma unroll
        for (int nt=0;nt<4;nt++)
            #pragma unroll
            for (int q=0;q<4;q++) acc[mt][nt][q]=0.f;

    // per-lane ldmatrix base offsets
    int within = lane & 7, blk = lane >> 3;
    uint32_t aBase = sb + OFF_AHI +
        (uint32_t)(((warp_m*64 + within + (blk&1)*8) * AP + (blk>>1)*8) * 2);
    uint32_t bBase = sb + OFF_BHI +
        (uint32_t)(((within + (blk&1)*8) * BP + warp_n*32 + (blk>>1)*8) * 2);

    for (int c = 0; c < 4; c++){
        int kc = c * 64;
        // stage A: 128 rows x 64 k (pairs), split hi/lo
        for (int idx = tid; idx < 128*32; idx += 256){
            int r = idx >> 5, kp = idx & 31;
            float2 x = *(const float2*)&hB[(size_t)r*Kk + kc + kp*2];
            __nv_bfloat162 hi, lo;
            hi.x = __float2bfloat16(x.x); lo.x = __float2bfloat16(x.x - __bfloat162float(hi.x));
            hi.y = __float2bfloat16(x.y); lo.y = __float2bfloat16(x.y - __bfloat162float(hi.y));
            uint32_t off = (uint32_t)((r*AP + kp*2) * 2);
            *(__nv_bfloat162*)(smem + OFF_AHI + off) = hi;
            *(__nv_bfloat162*)(smem + OFF_ALO + off) = lo;
        }
        // stage B: 64 k x 128 n (pairs), split hi/lo
        for (int idx = tid; idx < 64*64; idx += 256){
            int k = idx >> 6, np = idx & 63;
            float2 x = *(const float2*)&W[(size_t)(kc+k)*Ff + np*2];
            __nv_bfloat162 hi, lo;
            hi.x = __float2bfloat16(x.x); lo.x = __float2bfloat16(x.x - __bfloat162float(hi.x));
            hi.y = __float2bfloat16(x.y); lo.y = __float2bfloat16(x.y - __bfloat162float(hi.y));
            uint32_t off = (uint32_t)((k*BP + np*2) * 2);
            *(__nv_bfloat162*)(smem + OFF_BHI + off) = hi;
            *(__nv_bfloat162*)(smem + OFF_BLO + off) = lo;
        }
        __syncthreads();

        #pragma unroll
        for (int ks = 0; ks < 4; ks++){
            uint32_t ah[4][4], al[4][4];
            #pragma unroll
            for (int mt=0;mt<4;mt++){
                uint32_t ad = aBase + (uint32_t)(mt*16*AP*2 + ks*32);
                ldsm_x4 (ah[mt], ad);
                ldsm_x4 (al[mt], ad + (OFF_ALO-OFF_AHI));
            }
            uint32_t bh[2][4], bl[2][4];
            #pragma unroll
            for (int np=0;np<2;np++){
                uint32_t bd = bBase + (uint32_t)(np*32 + ks*16*BP*2);
                ldsm_x4t(bh[np], bd);
                ldsm_x4t(bl[np], bd + (OFF_BLO-OFF_BHI));
            }
            #pragma unroll
            for (int mt=0;mt<4;mt++){
                #pragma unroll
                for (int nt=0;nt<4;nt++){
                    const uint32_t* pbh = &bh[nt>>1][(nt&1)*2];
                    const uint32_t* pbl = &bl[nt>>1][(nt&1)*2];
                    mma16816(acc[mt][nt], ah[mt], pbh);
                    mma16816(acc[mt][nt], ah[mt], pbl);
                    mma16816(acc[mt][nt], al[mt], pbh);
                }
            }
        }
        __syncthreads();
    }

    // epilogue: store Wh (d-fragment layout)
    int g = lane >> 2, tig = lane & 3;
    #pragma unroll
    for (int mt=0;mt<4;mt++){
        int r0a = row0 + warp_m*64 + mt*16 + g;
        #pragma unroll
        for (int nt=0;nt<4;nt++){
            int col = warp_n*32 + nt*8 + 2*tig;
            float2 d01; d01.x = acc[mt][nt][0]; d01.y = acc[mt][nt][1];
            float2 d23; d23.x = acc[mt][nt][2]; d23.y = acc[mt][nt][3];
            *(float2*)&g_Wh[((size_t)b*Nn + r0a    )*Ff + col] = d01;
            *(float2*)&g_Wh[((size_t)b*Nn + r0a + 8)*Ff + col] = d23;
        }
    }
}

// ================= Kernel B: per-batch bitonic sort on key=-v + scalar scans ==
__global__ void sort_scan() {
    __shared__ float skey[2048];
    __shared__ int   sidx[2048];
    __shared__ float sa[2048];
    __shared__ float sb2[2048];
    __shared__ float st[2048];
    int b = blockIdx.x;
    int tid = threadIdx.x; // 1024

    for (int e=tid; e<2048; e+=1024){ skey[e] = -g_v[b*Nn+e]; sidx[e]=e; }
    __syncthreads();

    for (int k=2;k<=2048;k<<=1){
        for (int j=k>>1;j>0;j>>=1){
            for (int e=tid;e<2048;e+=1024){
                int ixj = e ^ j;
                if (ixj > e){
                    bool up = ((e & k) == 0);
                    float a=skey[e], c=skey[ixj];
                    if ((a > c) == up){
                        skey[e]=c; skey[ixj]=a;
                        int t1=sidx[e]; sidx[e]=sidx[ixj]; sidx[ixj]=t1;
                    }
                }
            }
            __syncthreads();
        }
    }

    for (int e=tid;e<2048;e+=1024){
        float kv = skey[e];
        float vv = -kv;
        float Ejv = __expf(vv);
        float Fjv = __expf(0.01f*vv);
        g_key [b*Nn+e]=kv;  g_perm[b*Nn+e]=sidx[e];
        g_Ej  [b*Nn+e]=Ejv; g_Fj  [b*Nn+e]=Fjv;
        sa[e]=Ejv; sb2[e]=Fjv;
    }
    __syncthreads();

    {
        float* src = sa; float* dst = st;
        for (int d=1; d<2048; d<<=1){
            for (int e=tid;e<2048;e+=1024)
                dst[e] = src[e] + (e>=d ? src[e-d] : 0.f);
            __syncthreads();
            float* tp=src; src=dst; dst=tp;
        }
        for (int e=tid;e<2048;e+=1024) g_PzE[b*Nn+e] = src[e];
        __syncthreads();
    }
    {
        float* src = sb2; float* dst = sa;
        for (int d=1; d<2048; d<<=1){
            for (int e=tid;e<2048;e+=1024)
                dst[e] = src[e] + (e>=d ? src[e-d] : 0.f);
            __syncthreads();
            float* tp=src; src=dst; dst=tp;
        }
        for (int e=tid;e<2048;e+=1024) g_PzF[b*Nn+e] = src[e];
    }
}

// ============ Kernel C1: chunk-local vector prefixes of Ej*Wh, Fj*Wh ==========
__global__ void prefix_chunks() {
    __shared__ int   sperm[CSZ];
    __shared__ float sE[CSZ], sF[CSZ];
    int b = blockIdx.y, ch = blockIdx.x, f = threadIdx.x; // 128 thr
    int base = ch*CSZ;
    if (f < CSZ){
        sperm[f]=g_perm[b*Nn+base+f];
        sE[f]=g_Ej[b*Nn+base+f];
        sF[f]=g_Fj[b*Nn+base+f];
    }
    __syncthreads();
    float ae=0.f, af=0.f;
    #pragma unroll 4
    for (int m=0;m<CSZ;m++){
        int j = sperm[m];
        float w = g_Wh[((size_t)b*Nn + j)*Ff + f];
        ae = fmaf(sE[m], w, ae);
        af = fmaf(sF[m], w, af);
        size_t o = ((size_t)b*Nn + base + m)*Ff + f;
        g_PE[o]=ae; g_PF[o]=af;
    }
    g_chE[((size_t)b*Ff+f)*NCH+ch]=ae;
    g_chF[((size_t)b*Ff+f)*NCH+ch]=af;
}

// ======== Kernel C2: warp-parallel exclusive scan of chunk totals =============
__global__ void scan_chunks(){
    int b=blockIdx.x;
    int lane=threadIdx.x, ty=threadIdx.y;
    int f = blockIdx.y*32 + ty;
    float ev = g_chE[((size_t)b*Ff+f)*NCH + lane];
    float fv = g_chF[((size_t)b*Ff+f)*NCH + lane];
    float ie = ev, iff = fv;
    #pragma unroll
    for (int s=1;s<32;s<<=1){
        float te = __shfl_up_sync(0xffffffffu, ie, s);
        float tf = __shfl_up_sync(0xffffffffu, iff, s);
        if (lane>=s){ ie+=te; iff+=tf; }
    }
    g_offE[((size_t)b*NCH+lane)*Ff+f] = ie - ev;
    g_offF[((size_t)b*NCH+lane)*Ff+f] = iff - fv;
    if (lane==31) g_TF[b*Ff+f] = iff;
}

// ================= Kernel D: binary search + combine ==========================
__global__ void finalize(float* __restrict__ out){
    __shared__ float skey[2048];
    int b  = blockIdx.y;
    int tx = threadIdx.x;  // 128 (feature)
    int ty = threadIdx.y;  // 8 rows per block
    int t  = ty*128+tx;
    for (int e=t; e<2048; e+=1024) skey[e]=g_key[b*Nn+e];
    __syncthreads();

    int row = blockIdx.x*8 + ty;
    float uu = g_u[b*Nn+row];
    int lo=0, hi=2048;
    while (lo<hi){ int mid=(lo+hi)>>1; if (skey[mid] < uu) lo=mid+1; else hi=mid; }
    int k = lo;

    float Ei = __expf(uu), Fi = __expf(0.01f*uu);
    float TFf = g_TF[b*Ff+tx];
    float TzF = g_PzF[b*Nn + 2047];

    float pe=0.f, pf=0.f, pze=0.f, pzf=0.f;
    if (k>0){
        int km = k-1, c = km>>6;
        size_t o = ((size_t)b*Nn+km)*Ff+tx;
        pe  = g_PE[o] + g_offE[(b*NCH+c)*Ff+tx];
        pf  = g_PF[o] + g_offF[(b*NCH+c)*Ff+tx];
        pze = g_PzE[b*Nn+km];
        pzf = g_PzF[b*Nn+km];
    }
    float num = Ei*pe + Fi*(TFf - pf);
    float den = Ei*pze + Fi*(TzF - pzf);
    out[((size_t)b*Nn+row)*Ff+tx] = num/den;
}

// ================= launch =================
extern "C" void kernel_launch(void* const* d_in, const int* in_sizes, int n_in,
                              void* d_out, int out_size) {
    const float* h  = (const float*)d_in[0];
    const float* W  = (const float*)d_in[1];
    const float* ai = (const float*)d_in[2];
    const float* aj = (const float*)d_in[3];
    float* out = (float*)d_out;

    cudaFuncSetAttribute(gemm_mma, cudaFuncAttributeMaxDynamicSharedMemorySize, SM_GEMM);

    wa_kernel    <<<32, 256>>>(W, ai, aj);
    uv_kernel    <<<2048, 256>>>(h);
    sort_scan    <<<Bb, 1024>>>();
    gemm_mma     <<<dim3(Nn/128, Bb), 256, SM_GEMM>>>(h, W);
    prefix_chunks<<<dim3(NCH, Bb), 128>>>();
    scan_chunks  <<<dim3(Bb, 4), dim3(32,32)>>>();
    finalize     <<<dim3(Nn/8, Bb), dim3(128,8)>>>(out);
}